// round 15
// baseline (speedup 1.0000x reference)
#include <cuda_runtime.h>
#include <cuda_bf16.h>
#include <math.h>
#include <stdint.h>

// Problem constants
#define BATCH 1024
#define NN 50
#define SS 50
#define HH 64
#define VOCAB 200000
#define VOUT 199999   // V-1 output columns

// Scratch: session embeddings + pre-split emb (bf16 hi/lo) + tile counters
__device__ float g_a[BATCH * HH];
__device__ __nv_bfloat16 g_ehi[VOCAB * HH];
__device__ __nv_bfloat16 g_elo[VOCAB * HH];
__device__ unsigned int g_tilecnt[8];

__device__ __forceinline__ float sigmoidf_(float x) {
    return 1.0f / (1.0f + expf(-x));
}

// hi = truncate-to-bf16 pair pack; lo = exact residual, RN to bf16 pair
static __device__ __forceinline__ uint32_t hi_pack(float x, float y) {
    return __byte_perm(__float_as_uint(x), __float_as_uint(y), 0x7632);
}
static __device__ __forceinline__ float lo_res(float x) {
    return x - __uint_as_float(__float_as_uint(x) & 0xFFFF0000u);
}
static __device__ __forceinline__ uint32_t lo_pack(float x, float y) {
    uint32_t r;
    asm("cvt.rn.bf16x2.f32 %0, %1, %2;" : "=r"(r)
        : "f"(lo_res(y)), "f"(lo_res(x)));   // low16 = cvt(x)
    return r;
}

// ===========================================================================
// Phase 0: split emb fp32 -> bf16 hi/lo + zero the dependency counters
// ===========================================================================
__global__ void __launch_bounds__(256) split_kernel(const float* __restrict__ emb)
{
    if (blockIdx.x == 0 && threadIdx.x < 8) g_tilecnt[threadIdx.x] = 0;
    int idx = blockIdx.x * 256 + threadIdx.x;
    if (idx < VOCAB * (HH / 4)) {
        float4 v = ((const float4*)emb)[idx];
        ((uint2*)g_ehi)[idx] = make_uint2(hi_pack(v.x, v.y), hi_pack(v.z, v.w));
        ((uint2*)g_elo)[idx] = make_uint2(lo_pack(v.x, v.y), lo_pack(v.z, v.w));
    }
}

// ===========================================================================
// Fused kernel with INTERLEAVED block order: per batch-tile group g,
// blocks [g*324 .. g*324+127] = session CTAs for sessions g*128..g*128+127,
// blocks [g*324+128 .. g*324+323] = gemm CTAs for batch tile g.
// Gemm CTAs co-reside with the NEXT tiles' sessions -> pipelined overlap.
// smem: 25472 floats = 101888 B -> 2 CTAs/SM for both roles.
// ===========================================================================
#define SM1_FLOATS 25472
#define SM1_BYTES (SM1_FLOATS * 4)
#define GROUP_BLOCKS 324               // 128 session + 196 gemm

__device__ __forceinline__ void fma4s_(float4& a, float s, const float4 w) {
    a.x += s * w.x; a.y += s * w.y; a.z += s * w.z; a.w += s * w.w;
}

// ---- GEMM constants (R11 design) ----
#define OFF_AHI 0
#define OFF_ALO 16384
#define OFF_E0H 32768
#define OFF_E0L 49152
#define OFF_E1H 65536
#define OFF_E1L 81920
#define T_VTILES 8
#define NVTILES 1563                    // ceil(VOUT/128)
#define VGROUPS 196                     // ceil(NVTILES/T_VTILES)

static __device__ __forceinline__ uint32_t smem_u32(const void* p) {
    uint32_t a;
    asm("{ .reg .u64 t; cvta.to.shared.u64 t, %1; cvt.u32.u64 %0, t; }"
        : "=r"(a) : "l"(p));
    return a;
}

static __device__ __forceinline__ uint32_t sw_addr(int r, int c) {
    return (uint32_t)(r * 128 + ((c ^ (r & 7)) << 4));
}

static __device__ __forceinline__ void ldsm_x4(
    uint32_t& r0, uint32_t& r1, uint32_t& r2, uint32_t& r3, uint32_t addr)
{
    asm volatile("ldmatrix.sync.aligned.m8n8.x4.shared.b16 {%0,%1,%2,%3}, [%4];"
                 : "=r"(r0), "=r"(r1), "=r"(r2), "=r"(r3) : "r"(addr));
}

static __device__ __forceinline__ void mma_bf16(
    float* c, const uint32_t* a, const uint32_t* b)
{
    asm volatile(
        "mma.sync.aligned.m16n8k16.row.col.f32.bf16.bf16.f32 "
        "{%0,%1,%2,%3}, {%4,%5,%6,%7}, {%8,%9}, {%0,%1,%2,%3};"
        : "+f"(c[0]), "+f"(c[1]), "+f"(c[2]), "+f"(c[3])
        : "r"(a[0]), "r"(a[1]), "r"(a[2]), "r"(a[3]), "r"(b[0]), "r"(b[1]));
}

#define CP_ASYNC16(dst, src) \
    asm volatile("cp.async.cg.shared.global [%0], [%1], 16;" \
                 :: "r"(dst), "l"(src))
#define CP_COMMIT()  asm volatile("cp.async.commit_group;" ::: "memory")
#define CP_WAIT(N)   asm volatile("cp.async.wait_group %0;" :: "n"(N) : "memory")

static __device__ __forceinline__ void prefetch_e(
    uint32_t smb, uint32_t offH, uint32_t offL, int vt, int tid)
{
    #pragma unroll
    for (int i = 0; i < 4; i++) {
        int idx = tid + i * 256;
        int r = idx >> 3, c = idx & 7;
        int grow = vt * 128 + r;
        if (grow < VOUT) {
            const char* sh = (const char*)g_ehi
                + ((size_t)(1 + grow) * 64 + c * 8) * 2;
            const char* sl = (const char*)g_elo
                + ((size_t)(1 + grow) * 64 + c * 8) * 2;
            uint32_t sa = sw_addr(r, c);
            CP_ASYNC16(smb + offH + sa, sh);
            CP_ASYNC16(smb + offL + sa, sl);
        }
    }
    CP_COMMIT();
}

__global__ void __launch_bounds__(256, 2) fused_kernel(
    const int* __restrict__ alias_inputs, const float* __restrict__ ain,
    const float* __restrict__ aou, const int* __restrict__ items,
    const int* __restrict__ mask, const float* __restrict__ emb,
    const float* __restrict__ einw, const float* __restrict__ einb,
    const float* __restrict__ eouw, const float* __restrict__ eoub,
    const float* __restrict__ biah, const float* __restrict__ boah,
    const float* __restrict__ igw, const float* __restrict__ igb,
    const float* __restrict__ hgw, const float* __restrict__ hgb,
    const float* __restrict__ fc1w, const float* __restrict__ fc1b,
    const float* __restrict__ fc2w, const float* __restrict__ fc2b,
    const float* __restrict__ fc3w, float* __restrict__ out)
{
    extern __shared__ float sm[];
    const int tid = threadIdx.x;
    const int grp = blockIdx.x / GROUP_BLOCKS;
    const int idx_in = blockIdx.x - grp * GROUP_BLOCKS;

    if (idx_in < 128) {
        // ===================== SESSION ROLE =====================
        float* sh  = sm;
        float* sb1 = sm + 3200;
        float* sb2 = sm + 6400;
        float* sb3 = sm + 9600;
        float* sb4 = sm + 12800;
        float* sb5 = sm + 16000;
        float* sw  = sm + 19200;
        float* sq1 = sm + 25344;
        float* salpha = sm + 25408;
        __shared__ int s_last;

        const int b = grp * 128 + idx_in;

        for (int e = tid; e < 2048; e += 256)
            ((float2*)sw)[e] = ((const float2*)einw)[e];
        for (int e = tid; e < NN * HH; e += 256) {
            int n = e >> 6, c = e & 63;
            sh[e] = emb[(size_t)items[b * NN + n] * HH + c];
        }
        __syncthreads();

        for (int p = tid; p < 400; p += 256) {
            int n0 = (p >> 4) * 2, c4 = (p & 15) * 4;
            float4 bse = *(const float4*)&einb[c4];
            float4 a0 = bse, a1 = bse;
            const float* h0 = sh + n0 * 64;
            const float* h1 = h0 + 64;
            #pragma unroll 8
            for (int k = 0; k < 64; k++) {
                float4 w = *(const float4*)&sw[k * 64 + c4];
                fma4s_(a0, h0[k], w);
                fma4s_(a1, h1[k], w);
            }
            *(float4*)&sb1[n0 * 64 + c4] = a0;
            *(float4*)&sb1[n0 * 64 + 64 + c4] = a1;
        }
        __syncthreads();
        for (int e = tid; e < 2048; e += 256)
            ((float2*)sw)[e] = ((const float2*)eouw)[e];
        __syncthreads();
        for (int p = tid; p < 400; p += 256) {
            int n0 = (p >> 4) * 2, c4 = (p & 15) * 4;
            float4 bse = *(const float4*)&eoub[c4];
            float4 a0 = bse, a1 = bse;
            const float* h0 = sh + n0 * 64;
            const float* h1 = h0 + 64;
            #pragma unroll 8
            for (int k = 0; k < 64; k++) {
                float4 w = *(const float4*)&sw[k * 64 + c4];
                fma4s_(a0, h0[k], w);
                fma4s_(a1, h1[k], w);
            }
            *(float4*)&sb2[n0 * 64 + c4] = a0;
            *(float4*)&sb2[n0 * 64 + 64 + c4] = a1;
        }
        __syncthreads();

        for (int p = tid; p < 400; p += 256) {
            int n0 = (p >> 4) * 2, c4 = (p & 15) * 4;
            float4 i0 = *(const float4*)&biah[c4];
            float4 i1 = i0;
            float4 o0 = *(const float4*)&boah[c4];
            float4 o1 = o0;
            const float* ar0 = ain + (size_t)b * 2500 + n0 * 50;
            const float* ar1 = ar0 + 50;
            const float* br0 = aou + (size_t)b * 2500 + n0 * 50;
            const float* br1 = br0 + 50;
            #pragma unroll 5
            for (int j = 0; j < 50; j++) {
                float4 t1 = *(const float4*)&sb1[j * 64 + c4];
                float4 t2 = *(const float4*)&sb2[j * 64 + c4];
                fma4s_(i0, ar0[j], t1);
                fma4s_(i1, ar1[j], t1);
                fma4s_(o0, br0[j], t2);
                fma4s_(o1, br1[j], t2);
            }
            *(float4*)&sb3[n0 * 64 + c4] = i0;
            *(float4*)&sb3[n0 * 64 + 64 + c4] = i1;
            *(float4*)&sb4[n0 * 64 + c4] = o0;
            *(float4*)&sb4[n0 * 64 + 64 + c4] = o1;
        }
        __syncthreads();

        for (int g = 0; g < 3; g++) {
            for (int hf = 0; hf < 2; hf++) {
                int gcol = g * 64 + hf * 32;
                for (int e = tid; e < 2048; e += 256) {
                    int k = e >> 4, cc2 = (e & 15) * 2;
                    *(float2*)&sw[k * 32 + cc2] =
                        *(const float2*)&igw[k * 192 + gcol + cc2];
                }
                for (int e = tid; e < 1024; e += 256) {
                    int k = e >> 4, cc2 = (e & 15) * 2;
                    *(float2*)&sw[4096 + k * 32 + cc2] =
                        *(const float2*)&hgw[k * 192 + gcol + cc2];
                }
                __syncthreads();

                if (tid < 200) {
                    int n0 = (tid >> 3) * 2, cc4 = (tid & 7) * 4;
                    float4 si0 = *(const float4*)&igb[gcol + cc4];
                    float4 si1 = si0;
                    float4 sh0 = *(const float4*)&hgb[gcol + cc4];
                    float4 sh1 = sh0;
                    const float* r30 = sb3 + n0 * 64;
                    const float* r31 = r30 + 64;
                    const float* r40 = sb4 + n0 * 64;
                    const float* r41 = r40 + 64;
                    const float* hr0 = sh + n0 * 64;
                    const float* hr1 = hr0 + 64;
                    #pragma unroll 8
                    for (int k = 0; k < 64; k++) {
                        float4 w1 = *(const float4*)&sw[k * 32 + cc4];
                        float4 w2 = *(const float4*)&sw[(64 + k) * 32 + cc4];
                        float4 wh = *(const float4*)&sw[4096 + k * 32 + cc4];
                        fma4s_(si0, r30[k], w1); fma4s_(si0, r40[k], w2);
                        fma4s_(si1, r31[k], w1); fma4s_(si1, r41[k], w2);
                        fma4s_(sh0, hr0[k], wh);
                        fma4s_(sh1, hr1[k], wh);
                    }
                    int e0 = n0 * 64 + hf * 32 + cc4;
                    int e1 = e0 + 64;
                    float s0v[4] = {si0.x, si0.y, si0.z, si0.w};
                    float s1v[4] = {si1.x, si1.y, si1.z, si1.w};
                    float h0v[4] = {sh0.x, sh0.y, sh0.z, sh0.w};
                    float h1v[4] = {sh1.x, sh1.y, sh1.z, sh1.w};
                    if (g == 0) {
                        #pragma unroll
                        for (int q = 0; q < 4; q++) {
                            sb1[e0 + q] = sigmoidf_(s0v[q] + h0v[q]);
                            sb1[e1 + q] = sigmoidf_(s1v[q] + h1v[q]);
                        }
                    } else if (g == 1) {
                        #pragma unroll
                        for (int q = 0; q < 4; q++) {
                            sb2[e0 + q] = sigmoidf_(s0v[q] + h0v[q]);
                            sb2[e1 + q] = sigmoidf_(s1v[q] + h1v[q]);
                        }
                    } else {
                        #pragma unroll
                        for (int q = 0; q < 4; q++) {
                            float ng0 = tanhf(s0v[q] + sb1[e0 + q] * h0v[q]);
                            sb5[e0 + q] = ng0 + sb2[e0 + q] * (sh[e0 + q] - ng0);
                            float ng1 = tanhf(s1v[q] + sb1[e1 + q] * h1v[q]);
                            sb5[e1 + q] = ng1 + sb2[e1 + q] * (sh[e1 + q] - ng1);
                        }
                    }
                }
                __syncthreads();
            }
        }

        if (tid == 0) {
            int m = 0;
            for (int s = 0; s < SS; s++) m += mask[b * SS + s];
            s_last = m - 1;
        }
        for (int e = tid; e < SS * HH; e += 256) {
            int s = e >> 6, c = e & 63;
            sb3[e] = sb5[alias_inputs[b * SS + s] * 64 + c];
        }
        for (int e = tid; e < 2048; e += 256)
            ((float2*)sw)[e] = ((const float2*)fc2w)[e];
        __syncthreads();

        if (tid < 64) {
            int c = tid;
            float q = fc1b[c];
            const float* htr = sb3 + s_last * 64;
            #pragma unroll 8
            for (int k = 0; k < 64; k++) q += htr[k] * fc1w[k * 64 + c];
            sq1[c] = q;
        }
        __syncthreads();

        for (int p = tid; p < 400; p += 256) {
            int s0 = (p >> 4) * 2, c4 = (p & 15) * 4;
            float4 q0 = *(const float4*)&fc2b[c4];
            float4 q1v = q0;
            const float* r0 = sb3 + s0 * 64;
            const float* r1 = r0 + 64;
            #pragma unroll 8
            for (int k = 0; k < 64; k++) {
                float4 w = *(const float4*)&sw[k * 64 + c4];
                fma4s_(q0, r0[k], w);
                fma4s_(q1v, r1[k], w);
            }
            int e0 = s0 * 64 + c4, e1 = e0 + 64;
            float q0v[4] = {q0.x, q0.y, q0.z, q0.w};
            float q1a[4] = {q1v.x, q1v.y, q1v.z, q1v.w};
            #pragma unroll
            for (int q = 0; q < 4; q++) {
                sb4[e0 + q] = sigmoidf_(sq1[c4 + q] + q0v[q]) * fc3w[c4 + q];
                sb4[e1 + q] = sigmoidf_(sq1[c4 + q] + q1a[q]) * fc3w[c4 + q];
            }
        }
        __syncthreads();

        if (tid < SS) {
            float al = 0.0f;
            #pragma unroll 8
            for (int c = 0; c < 64; c++) al += sb4[tid * 64 + c];
            salpha[tid] = al * (float)mask[b * SS + tid];
        }
        __syncthreads();

        if (tid < 64) {
            float a = 0.0f;
            #pragma unroll 5
            for (int s = 0; s < SS; s++) a += salpha[s] * sb3[s * 64 + tid];
            g_a[b * 64 + tid] = a;
        }
        __syncthreads();
        if (tid == 0) {
            __threadfence();
            atomicAdd(&g_tilecnt[grp], 1u);
        }
    } else {
        // ===================== GEMM ROLE =====================
        char* smc = (char*)sm;
        const uint32_t smb = smem_u32(smc);
        const int wid = tid >> 5;
        const int lid = tid & 31;
        const int warp_m = wid & 1;
        const int warp_n = wid >> 1;
        const int btile = grp;
        const int vgrp = idx_in - 128;        // 0..195
        const int b0 = btile * 128;
        const int vt0 = vgrp * T_VTILES;
        const int nv = (NVTILES - vt0 < T_VTILES) ? (NVTILES - vt0) : T_VTILES;
        if (nv <= 0) return;

        // Start E prefetch (independent of g_a)
        prefetch_e(smb, OFF_E0H, OFF_E0L, vt0, tid);

        // Wait for this batch tile's 128 session blocks
        if (tid == 0) {
            unsigned ns = 64;
            while (atomicAdd(&g_tilecnt[btile], 0u) < 128u) {
                __nanosleep(ns);
                if (ns < 4096) ns <<= 1;
            }
            __threadfence();
        }
        __syncthreads();

        // Stage A tile: a[b0+m][k] -> hi/lo bf16 swizzled
        for (int idx = tid; idx < 128 * 16; idx += 256) {
            int m = idx >> 4, q = idx & 15;
            float4 v = *(const float4*)&g_a[(b0 + m) * 64 + q * 4];
            uint32_t a = sw_addr(m, q >> 1) + (q & 1) * 8;
            *(uint2*)(smc + OFF_AHI + a) =
                make_uint2(hi_pack(v.x, v.y), hi_pack(v.z, v.w));
            *(uint2*)(smc + OFF_ALO + a) =
                make_uint2(lo_pack(v.x, v.y), lo_pack(v.z, v.w));
        }

        const int a_row = (lid & 7) + ((lid >> 3) & 1) * 8;
        const int a_c8  = (lid >> 4) & 1;
        const int b_row = (lid & 7) + ((lid >> 4) & 1) * 8;
        const int b_c8  = (lid >> 3) & 1;

        for (int t = 0; t < nv; t++) {
            int vt = vt0 + t;
            if (t + 1 < nv) {
                if ((t + 1) & 1) prefetch_e(smb, OFF_E1H, OFF_E1L, vt + 1, tid);
                else             prefetch_e(smb, OFF_E0H, OFF_E0L, vt + 1, tid);
                CP_WAIT(1);
            } else {
                CP_WAIT(0);
            }
            __syncthreads();

            const uint32_t eH = smb + ((t & 1) ? OFF_E1H : OFF_E0H);
            const uint32_t eL = smb + ((t & 1) ? OFF_E1L : OFF_E0L);

            float c[4][4][4];
            #pragma unroll
            for (int i = 0; i < 4; i++)
                #pragma unroll
                for (int j = 0; j < 4; j++)
                    #pragma unroll
                    for (int q = 0; q < 4; q++) c[i][j][q] = 0.0f;

            #pragma unroll
            for (int ks = 0; ks < 4; ks++) {
                uint32_t ah[4][4], al[4][4];
                #pragma unroll
                for (int mf = 0; mf < 4; mf++) {
                    int rm = warp_m * 64 + mf * 16 + a_row;
                    uint32_t sa = sw_addr(rm, ks * 2 + a_c8);
                    ldsm_x4(ah[mf][0], ah[mf][1], ah[mf][2], ah[mf][3],
                            smb + OFF_AHI + sa);
                    ldsm_x4(al[mf][0], al[mf][1], al[mf][2], al[mf][3],
                            smb + OFF_ALO + sa);
                }
                #pragma unroll
                for (int np = 0; np < 2; np++) {
                    int rn = warp_n * 32 + np * 16 + b_row;
                    uint32_t sa = sw_addr(rn, ks * 2 + b_c8);
                    uint32_t bh[4], bl[4];
                    ldsm_x4(bh[0], bh[1], bh[2], bh[3], eH + sa);
                    ldsm_x4(bl[0], bl[1], bl[2], bl[3], eL + sa);
                    #pragma unroll
                    for (int h = 0; h < 2; h++) {
                        int nf = np * 2 + h;
                        #pragma unroll
                        for (int mf = 0; mf < 4; mf++) {
                            mma_bf16(c[mf][nf], ah[mf], bh + 2 * h);
                            mma_bf16(c[mf][nf], ah[mf], bl + 2 * h);
                            mma_bf16(c[mf][nf], al[mf], bh + 2 * h);
                        }
                    }
                }
            }

            // Epilogue: stage C through freed current-E buffer, coalesced STG
            __syncthreads();
            float* stg = (float*)(smc + ((t & 1) ? OFF_E1H : OFF_E0H));
            const int v0 = vt * 128;
            #pragma unroll
            for (int h = 0; h < 2; h++) {
                if (warp_m == h) {
                    int q = lid >> 2;
                    int swz = q << 3;
                    #pragma unroll
                    for (int mf = 0; mf < 4; mf++) {
                        int r0 = mf * 16 + q;
                        #pragma unroll
                        for (int nf = 0; nf < 4; nf++) {
                            int col = warp_n * 32 + (lid & 3) * 2 + nf * 8;
                            int sc = col ^ swz;
                            *(float2*)&stg[r0 * 128 + sc] =
                                make_float2(c[mf][nf][0], c[mf][nf][1]);
                            *(float2*)&stg[(r0 + 8) * 128 + sc] =
                                make_float2(c[mf][nf][2], c[mf][nf][3]);
                        }
                    }
                }
                __syncthreads();
                #pragma unroll
                for (int i = 0; i < 8; i++) {
                    int r = wid * 8 + i;
                    int swz = (r & 7) << 3;
                    float* orow = out + (size_t)(b0 + h * 64 + r) * VOUT;
                    #pragma unroll
                    for (int j = 0; j < 4; j++) {
                        int col = lid + 32 * j;
                        int gcol = v0 + col;
                        if (gcol < VOUT)
                            orow[gcol] = stg[r * 128 + (col ^ swz)];
                    }
                }
                __syncthreads();
            }
        }
    }
}

// ===========================================================================
extern "C" void kernel_launch(void* const* d_in, const int* in_sizes, int n_in,
                              void* d_out, int out_size)
{
    const int*   alias_inputs = (const int*)  d_in[0];
    const float* ain   = (const float*)d_in[1];
    const float* aou   = (const float*)d_in[2];
    const int*   items = (const int*)  d_in[3];
    const int*   mask  = (const int*)  d_in[4];
    /* d_in[5] edge_index unused */
    const float* emb   = (const float*)d_in[6];
    const float* einw  = (const float*)d_in[7];
    const float* einb  = (const float*)d_in[8];
    const float* eouw  = (const float*)d_in[9];
    const float* eoub  = (const float*)d_in[10];
    const float* biah  = (const float*)d_in[11];
    const float* boah  = (const float*)d_in[12];
    const float* igw   = (const float*)d_in[13];
    const float* igb   = (const float*)d_in[14];
    const float* hgw   = (const float*)d_in[15];
    const float* hgb   = (const float*)d_in[16];
    const float* fc1w  = (const float*)d_in[17];
    const float* fc1b  = (const float*)d_in[18];
    const float* fc2w  = (const float*)d_in[19];
    const float* fc2b  = (const float*)d_in[20];
    const float* fc3w  = (const float*)d_in[21];
    float* out = (float*)d_out;

    cudaFuncSetAttribute(fused_kernel,
                         cudaFuncAttributeMaxDynamicSharedMemorySize,
                         SM1_BYTES);

    split_kernel<<<(VOCAB * 16 + 255) / 256, 256>>>(emb);

    int total_blocks = 8 * GROUP_BLOCKS;   // 2592: interleaved groups
    fused_kernel<<<total_blocks, 256, SM1_BYTES>>>(
        alias_inputs, ain, aou, items, mask, emb,
        einw, einb, eouw, eoub, biah, boah,
        igw, igb, hgw, hgb, fc1w, fc1b, fc2w, fc2b, fc3w, out);
}

// round 17
// speedup vs baseline: 1.6126x; 1.6126x over previous
#include <cuda_runtime.h>
#include <cuda_bf16.h>
#include <math.h>
#include <stdint.h>

// Problem constants
#define BATCH 1024
#define NN 50
#define SS 50
#define HH 64
#define VOCAB 200000
#define VOUT 199999   // V-1 output columns

// Scratch: session embeddings + pre-split emb (bf16 hi/lo)
__device__ float g_a[BATCH * HH];
__device__ __nv_bfloat16 g_ehi[VOCAB * HH];
__device__ __nv_bfloat16 g_elo[VOCAB * HH];

__device__ __forceinline__ float sigmoidf_(float x) {
    return 1.0f / (1.0f + expf(-x));
}

// hi = truncate-to-bf16 pair pack; lo = exact residual, RN to bf16 pair
static __device__ __forceinline__ uint32_t hi_pack(float x, float y) {
    return __byte_perm(__float_as_uint(x), __float_as_uint(y), 0x7632);
}
static __device__ __forceinline__ float lo_res(float x) {
    return x - __uint_as_float(__float_as_uint(x) & 0xFFFF0000u);
}
static __device__ __forceinline__ uint32_t lo_pack(float x, float y) {
    uint32_t r;
    asm("cvt.rn.bf16x2.f32 %0, %1, %2;" : "=r"(r)
        : "f"(lo_res(y)), "f"(lo_res(x)));   // low16 = cvt(x)
    return r;
}

// ===========================================================================
// Phase 0: split emb fp32 -> bf16 hi/lo  (one float4 per thread)
// ===========================================================================
__global__ void __launch_bounds__(256) split_kernel(const float* __restrict__ emb)
{
    int idx = blockIdx.x * 256 + threadIdx.x;
    if (idx < VOCAB * (HH / 4)) {
        float4 v = ((const float4*)emb)[idx];
        ((uint2*)g_ehi)[idx] = make_uint2(hi_pack(v.x, v.y), hi_pack(v.z, v.w));
        ((uint2*)g_elo)[idx] = make_uint2(lo_pack(v.x, v.y), lo_pack(v.z, v.w));
    }
}

// ===========================================================================
// Phase 1: per-session GGNN cell + attention readout -> g_a
// 2-row x 4-col microtiles; fused t1/t2 pass (ein+eou staged together, h
// read once); h_new overwrites sb1 (sb5 dropped).
// smem: 24320 floats = 97280 B -> 2 CTAs/SM
// ===========================================================================
#define SM1_FLOATS 24320

__device__ __forceinline__ void fma4s_(float4& a, float s, const float4 w) {
    a.x += s * w.x; a.y += s * w.y; a.z += s * w.z; a.w += s * w.w;
}

__global__ void __launch_bounds__(256, 2) session_kernel(
    const int* __restrict__ alias_inputs, const float* __restrict__ ain,
    const float* __restrict__ aou, const int* __restrict__ items,
    const int* __restrict__ mask, const float* __restrict__ emb,
    const float* __restrict__ einw, const float* __restrict__ einb,
    const float* __restrict__ eouw, const float* __restrict__ eoub,
    const float* __restrict__ biah, const float* __restrict__ boah,
    const float* __restrict__ igw, const float* __restrict__ igb,
    const float* __restrict__ hgw, const float* __restrict__ hgb,
    const float* __restrict__ fc1w, const float* __restrict__ fc1b,
    const float* __restrict__ fc2w, const float* __restrict__ fc2b,
    const float* __restrict__ fc3w)
{
    extern __shared__ float sm[];
    float* sh  = sm;                 // h [50][64]
    float* sb1 = sm + 3200;          // t1 -> resetgate -> h_new
    float* sb2 = sm + 6400;          // t2 -> inputgate
    float* sb3 = sm + 9600;          // input_in -> seq
    float* sb4 = sm + 12800;         // input_out -> attn vals
    float* sw  = sm + 16000;         // 8192 floats weight staging
    float* sq1 = sm + 24192;
    float* salpha = sm + 24256;
    __shared__ int s_last;

    const int b = blockIdx.x;
    const int tid = threadIdx.x;

    // Stage ein_w AND eou_w together; gather h = emb[items]
    for (int e = tid; e < 2048; e += 256) {
        ((float2*)sw)[e]        = ((const float2*)einw)[e];
        ((float2*)sw)[2048 + e] = ((const float2*)eouw)[e];
    }
    for (int e = tid; e < NN * HH; e += 256) {
        int n = e >> 6, c = e & 63;
        sh[e] = emb[(size_t)items[b * NN + n] * HH + c];
    }
    __syncthreads();

    // ---- FUSED t1/t2 = h @ {ein,eou}_w + bias  (2 rows x 4 cols / thread)
    for (int p = tid; p < 400; p += 256) {
        int n0 = (p >> 4) * 2, c4 = (p & 15) * 4;
        float4 t1a = *(const float4*)&einb[c4];
        float4 t1b = t1a;
        float4 t2a = *(const float4*)&eoub[c4];
        float4 t2b = t2a;
        const float* h0 = sh + n0 * 64;
        const float* h1 = h0 + 64;
        #pragma unroll 8
        for (int k = 0; k < 64; k++) {
            float x0 = h0[k], x1 = h1[k];
            float4 w1 = *(const float4*)&sw[k * 64 + c4];
            float4 w2 = *(const float4*)&sw[4096 + k * 64 + c4];
            fma4s_(t1a, x0, w1);
            fma4s_(t1b, x1, w1);
            fma4s_(t2a, x0, w2);
            fma4s_(t2b, x1, w2);
        }
        *(float4*)&sb1[n0 * 64 + c4] = t1a;
        *(float4*)&sb1[n0 * 64 + 64 + c4] = t1b;
        *(float4*)&sb2[n0 * 64 + c4] = t2a;
        *(float4*)&sb2[n0 * 64 + 64 + c4] = t2b;
    }
    __syncthreads();

    // ---- input_in/input_out (2 rows x 4 cols; t1/t2 LDS shared across rows)
    for (int p = tid; p < 400; p += 256) {
        int n0 = (p >> 4) * 2, c4 = (p & 15) * 4;
        float4 i0 = *(const float4*)&biah[c4];
        float4 i1 = i0;
        float4 o0 = *(const float4*)&boah[c4];
        float4 o1 = o0;
        const float* ar0 = ain + (size_t)b * 2500 + n0 * 50;
        const float* ar1 = ar0 + 50;
        const float* br0 = aou + (size_t)b * 2500 + n0 * 50;
        const float* br1 = br0 + 50;
        #pragma unroll 5
        for (int j = 0; j < 50; j++) {
            float4 t1 = *(const float4*)&sb1[j * 64 + c4];
            float4 t2 = *(const float4*)&sb2[j * 64 + c4];
            fma4s_(i0, ar0[j], t1);
            fma4s_(i1, ar1[j], t1);
            fma4s_(o0, br0[j], t2);
            fma4s_(o1, br1[j], t2);
        }
        *(float4*)&sb3[n0 * 64 + c4] = i0;
        *(float4*)&sb3[n0 * 64 + 64 + c4] = i1;
        *(float4*)&sb4[n0 * 64 + c4] = o0;
        *(float4*)&sb4[n0 * 64 + 64 + c4] = o1;
    }
    __syncthreads();

    // ---- GRU gates: 3 gates x 2 half-col chunks; 2 rows x 4 cols / thread
    // g==0 resetgate -> sb1 (t1 dead), g==1 inputgate -> sb2 (t2 dead),
    // g==2 h_new -> sb1 (resetgate consumed element-wise before overwrite)
    for (int g = 0; g < 3; g++) {
        for (int hf = 0; hf < 2; hf++) {
            int gcol = g * 64 + hf * 32;
            for (int e = tid; e < 2048; e += 256) {
                int k = e >> 4, cc2 = (e & 15) * 2;
                *(float2*)&sw[k * 32 + cc2] =
                    *(const float2*)&igw[k * 192 + gcol + cc2];
            }
            for (int e = tid; e < 1024; e += 256) {
                int k = e >> 4, cc2 = (e & 15) * 2;
                *(float2*)&sw[4096 + k * 32 + cc2] =
                    *(const float2*)&hgw[k * 192 + gcol + cc2];
            }
            __syncthreads();

            if (tid < 200) {
                int n0 = (tid >> 3) * 2, cc4 = (tid & 7) * 4;
                float4 si0 = *(const float4*)&igb[gcol + cc4];
                float4 si1 = si0;
                float4 sh0 = *(const float4*)&hgb[gcol + cc4];
                float4 sh1 = sh0;
                const float* r30 = sb3 + n0 * 64;
                const float* r31 = r30 + 64;
                const float* r40 = sb4 + n0 * 64;
                const float* r41 = r40 + 64;
                const float* hr0 = sh + n0 * 64;
                const float* hr1 = hr0 + 64;
                #pragma unroll 8
                for (int k = 0; k < 64; k++) {
                    float4 w1 = *(const float4*)&sw[k * 32 + cc4];
                    float4 w2 = *(const float4*)&sw[(64 + k) * 32 + cc4];
                    float4 wh = *(const float4*)&sw[4096 + k * 32 + cc4];
                    fma4s_(si0, r30[k], w1); fma4s_(si0, r40[k], w2);
                    fma4s_(si1, r31[k], w1); fma4s_(si1, r41[k], w2);
                    fma4s_(sh0, hr0[k], wh);
                    fma4s_(sh1, hr1[k], wh);
                }
                int e0 = n0 * 64 + hf * 32 + cc4;
                int e1 = e0 + 64;
                float s0v[4] = {si0.x, si0.y, si0.z, si0.w};
                float s1v[4] = {si1.x, si1.y, si1.z, si1.w};
                float h0v[4] = {sh0.x, sh0.y, sh0.z, sh0.w};
                float h1v[4] = {sh1.x, sh1.y, sh1.z, sh1.w};
                if (g == 0) {
                    #pragma unroll
                    for (int q = 0; q < 4; q++) {
                        sb1[e0 + q] = sigmoidf_(s0v[q] + h0v[q]);
                        sb1[e1 + q] = sigmoidf_(s1v[q] + h1v[q]);
                    }
                } else if (g == 1) {
                    #pragma unroll
                    for (int q = 0; q < 4; q++) {
                        sb2[e0 + q] = sigmoidf_(s0v[q] + h0v[q]);
                        sb2[e1 + q] = sigmoidf_(s1v[q] + h1v[q]);
                    }
                } else {
                    #pragma unroll
                    for (int q = 0; q < 4; q++) {
                        float ng0 = tanhf(s0v[q] + sb1[e0 + q] * h0v[q]);
                        sb1[e0 + q] = ng0 + sb2[e0 + q] * (sh[e0 + q] - ng0);
                        float ng1 = tanhf(s1v[q] + sb1[e1 + q] * h1v[q]);
                        sb1[e1 + q] = ng1 + sb2[e1 + q] * (sh[e1 + q] - ng1);
                    }
                }
            }
            __syncthreads();
        }
    }

    // ---- attention readout, h_final = sb1 ----
    if (tid == 0) {
        int m = 0;
        for (int s = 0; s < SS; s++) m += mask[b * SS + s];
        s_last = m - 1;
    }
    for (int e = tid; e < SS * HH; e += 256) {
        int s = e >> 6, c = e & 63;
        sb3[e] = sb1[alias_inputs[b * SS + s] * 64 + c];
    }
    for (int e = tid; e < 2048; e += 256)
        ((float2*)sw)[e] = ((const float2*)fc2w)[e];
    __syncthreads();

    if (tid < 64) {
        int c = tid;
        float q = fc1b[c];
        const float* htr = sb3 + s_last * 64;
        #pragma unroll 8
        for (int k = 0; k < 64; k++) q += htr[k] * fc1w[k * 64 + c];
        sq1[c] = q;
    }
    __syncthreads();

    // vals = sigmoid(q1 + seq@fc2 + b) * fc3_w  (2 rows x 4 cols / thread)
    for (int p = tid; p < 400; p += 256) {
        int s0 = (p >> 4) * 2, c4 = (p & 15) * 4;
        float4 q0 = *(const float4*)&fc2b[c4];
        float4 q1v = q0;
        const float* r0 = sb3 + s0 * 64;
        const float* r1 = r0 + 64;
        #pragma unroll 8
        for (int k = 0; k < 64; k++) {
            float4 w = *(const float4*)&sw[k * 64 + c4];
            fma4s_(q0, r0[k], w);
            fma4s_(q1v, r1[k], w);
        }
        int e0 = s0 * 64 + c4, e1 = e0 + 64;
        float q0v[4] = {q0.x, q0.y, q0.z, q0.w};
        float q1a[4] = {q1v.x, q1v.y, q1v.z, q1v.w};
        #pragma unroll
        for (int q = 0; q < 4; q++) {
            sb4[e0 + q] = sigmoidf_(sq1[c4 + q] + q0v[q]) * fc3w[c4 + q];
            sb4[e1 + q] = sigmoidf_(sq1[c4 + q] + q1a[q]) * fc3w[c4 + q];
        }
    }
    __syncthreads();

    if (tid < SS) {
        float al = 0.0f;
        #pragma unroll 8
        for (int c = 0; c < 64; c++) al += sb4[tid * 64 + c];
        salpha[tid] = al * (float)mask[b * SS + tid];
    }
    __syncthreads();

    if (tid < 64) {
        float a = 0.0f;
        #pragma unroll 5
        for (int s = 0; s < SS; s++) a += salpha[s] * sb3[s * 64 + tid];
        g_a[b * 64 + tid] = a;
    }
}

// ===========================================================================
// Phase 2: mma.sync bf16 split GEMM (R11/R13, best measured — do not touch)
//   out = Ahi*Ehi + Ahi*Elo + Alo*Ehi, staged coalesced epilogue
// ===========================================================================

#define OFF_AHI 0
#define OFF_ALO 16384
#define OFF_E0H 32768
#define OFF_E0L 49152
#define OFF_E1H 65536
#define OFF_E1L 81920
#define GT_BYTES 98304
#define T_VTILES 8
#define NVTILES 1563                    // ceil(VOUT/128)

static __device__ __forceinline__ uint32_t smem_u32(const void* p) {
    uint32_t a;
    asm("{ .reg .u64 t; cvta.to.shared.u64 t, %1; cvt.u32.u64 %0, t; }"
        : "=r"(a) : "l"(p));
    return a;
}

// swizzled byte address of 16B chunk c in row r (row pitch 128B)
static __device__ __forceinline__ uint32_t sw_addr(int r, int c) {
    return (uint32_t)(r * 128 + ((c ^ (r & 7)) << 4));
}

static __device__ __forceinline__ void ldsm_x4(
    uint32_t& r0, uint32_t& r1, uint32_t& r2, uint32_t& r3, uint32_t addr)
{
    asm volatile("ldmatrix.sync.aligned.m8n8.x4.shared.b16 {%0,%1,%2,%3}, [%4];"
                 : "=r"(r0), "=r"(r1), "=r"(r2), "=r"(r3) : "r"(addr));
}

static __device__ __forceinline__ void mma_bf16(
    float* c, const uint32_t* a, const uint32_t* b)
{
    asm volatile(
        "mma.sync.aligned.m16n8k16.row.col.f32.bf16.bf16.f32 "
        "{%0,%1,%2,%3}, {%4,%5,%6,%7}, {%8,%9}, {%0,%1,%2,%3};"
        : "+f"(c[0]), "+f"(c[1]), "+f"(c[2]), "+f"(c[3])
        : "r"(a[0]), "r"(a[1]), "r"(a[2]), "r"(a[3]), "r"(b[0]), "r"(b[1]));
}

#define CP_ASYNC16(dst, src) \
    asm volatile("cp.async.cg.shared.global [%0], [%1], 16;" \
                 :: "r"(dst), "l"(src))
#define CP_COMMIT()  asm volatile("cp.async.commit_group;" ::: "memory")
#define CP_WAIT(N)   asm volatile("cp.async.wait_group %0;" :: "n"(N) : "memory")

// prefetch one E tile (hi+lo, 128 rows x 64 bf16) into swizzled smem
static __device__ __forceinline__ void prefetch_e(
    uint32_t smb, uint32_t offH, uint32_t offL, int vt, int tid)
{
    #pragma unroll
    for (int i = 0; i < 4; i++) {
        int idx = tid + i * 256;
        int r = idx >> 3, c = idx & 7;          // 16B chunk c of row r
        int grow = vt * 128 + r;
        if (grow < VOUT) {
            const char* sh = (const char*)g_ehi
                + ((size_t)(1 + grow) * 64 + c * 8) * 2;
            const char* sl = (const char*)g_elo
                + ((size_t)(1 + grow) * 64 + c * 8) * 2;
            uint32_t sa = sw_addr(r, c);
            CP_ASYNC16(smb + offH + sa, sh);
            CP_ASYNC16(smb + offL + sa, sl);
        }
    }
    CP_COMMIT();
}

__global__ void __launch_bounds__(256, 2) gemm_mma_kernel(
    float* __restrict__ out)
{
    extern __shared__ char smc[];
    const uint32_t smb = smem_u32(smc);
    const int tid = threadIdx.x;
    const int wid = tid >> 5;
    const int lid = tid & 31;
    const int warp_m = wid & 1;        // 0..1 -> 64-row block
    const int warp_n = wid >> 1;       // 0..3 -> 32-col block
    const int b0 = blockIdx.x * 128;   // batch tile (fast dim -> emb L2 reuse)
    const int vt0 = blockIdx.y * T_VTILES;
    const int nv = (NVTILES - vt0 < T_VTILES) ? (NVTILES - vt0) : T_VTILES;

    // ---- Stage A tile once: a[b0+m][k] -> hi/lo bf16 swizzled
    for (int idx = tid; idx < 128 * 16; idx += 256) {
        int m = idx >> 4, q = idx & 15;         // 4-elem group q
        float4 v = *(const float4*)&g_a[(b0 + m) * 64 + q * 4];
        uint32_t a = sw_addr(m, q >> 1) + (q & 1) * 8;
        *(uint2*)(smc + OFF_AHI + a) =
            make_uint2(hi_pack(v.x, v.y), hi_pack(v.z, v.w));
        *(uint2*)(smc + OFF_ALO + a) =
            make_uint2(lo_pack(v.x, v.y), lo_pack(v.z, v.w));
    }

    prefetch_e(smb, OFF_E0H, OFF_E0L, vt0, tid);

    // ldmatrix lane address components
    const int a_row = (lid & 7) + ((lid >> 3) & 1) * 8;
    const int a_c8  = (lid >> 4) & 1;
    const int b_row = (lid & 7) + ((lid >> 4) & 1) * 8;
    const int b_c8  = (lid >> 3) & 1;

    for (int t = 0; t < nv; t++) {
        int vt = vt0 + t;
        if (t + 1 < nv) {
            if ((t + 1) & 1) prefetch_e(smb, OFF_E1H, OFF_E1L, vt + 1, tid);
            else             prefetch_e(smb, OFF_E0H, OFF_E0L, vt + 1, tid);
            CP_WAIT(1);
        } else {
            CP_WAIT(0);
        }
        __syncthreads();

        const uint32_t eH = smb + ((t & 1) ? OFF_E1H : OFF_E0H);
        const uint32_t eL = smb + ((t & 1) ? OFF_E1L : OFF_E0L);

        float c[4][4][4];
        #pragma unroll
        for (int i = 0; i < 4; i++)
            #pragma unroll
            for (int j = 0; j < 4; j++)
                #pragma unroll
                for (int q = 0; q < 4; q++) c[i][j][q] = 0.0f;

        #pragma unroll
        for (int ks = 0; ks < 4; ks++) {
            uint32_t ah[4][4], al[4][4];
            #pragma unroll
            for (int mf = 0; mf < 4; mf++) {
                int rm = warp_m * 64 + mf * 16 + a_row;
                uint32_t sa = sw_addr(rm, ks * 2 + a_c8);
                ldsm_x4(ah[mf][0], ah[mf][1], ah[mf][2], ah[mf][3],
                        smb + OFF_AHI + sa);
                ldsm_x4(al[mf][0], al[mf][1], al[mf][2], al[mf][3],
                        smb + OFF_ALO + sa);
            }
            #pragma unroll
            for (int np = 0; np < 2; np++) {
                int rn = warp_n * 32 + np * 16 + b_row;
                uint32_t sa = sw_addr(rn, ks * 2 + b_c8);
                uint32_t bh[4], bl[4];
                ldsm_x4(bh[0], bh[1], bh[2], bh[3], eH + sa);
                ldsm_x4(bl[0], bl[1], bl[2], bl[3], eL + sa);
                #pragma unroll
                for (int h = 0; h < 2; h++) {
                    int nf = np * 2 + h;
                    #pragma unroll
                    for (int mf = 0; mf < 4; mf++) {
                        mma_bf16(c[mf][nf], ah[mf], bh + 2 * h);
                        mma_bf16(c[mf][nf], ah[mf], bl + 2 * h);
                        mma_bf16(c[mf][nf], al[mf], bh + 2 * h);
                    }
                }
            }
        }

        // ---- Epilogue: stage C through the freed current-E buffer (32KB),
        // two 64-row passes, then row-contiguous coalesced stores.
        __syncthreads();   // all mainloop reads of current E done
        float* stg = (float*)(smc + ((t & 1) ? OFF_E1H : OFF_E0H));
        const int v0 = vt * 128;
        #pragma unroll
        for (int h = 0; h < 2; h++) {
            if (warp_m == h) {
                int q = lid >> 2;               // 0..7, also row&7
                int swz = q << 3;               // fp32-elem swizzle, bits 3-5
                #pragma unroll
                for (int mf = 0; mf < 4; mf++) {
                    int r0 = mf * 16 + q;
                    #pragma unroll
                    for (int nf = 0; nf < 4; nf++) {
                        int col = warp_n * 32 + (lid & 3) * 2 + nf * 8;
                        int sc = col ^ swz;
                        *(float2*)&stg[r0 * 128 + sc] =
                            make_float2(c[mf][nf][0], c[mf][nf][1]);
                        *(float2*)&stg[(r0 + 8) * 128 + sc] =
                            make_float2(c[mf][nf][2], c[mf][nf][3]);
                    }
                }
            }
            __syncthreads();
            // all 8 warps store rows h*64 .. h*64+63 (8 rows each, coalesced)
            #pragma unroll
            for (int i = 0; i < 8; i++) {
                int r = wid * 8 + i;
                int swz = (r & 7) << 3;
                float* orow = out + (size_t)(b0 + h * 64 + r) * VOUT;
                #pragma unroll
                for (int j = 0; j < 4; j++) {
                    int col = lid + 32 * j;
                    int gcol = v0 + col;
                    if (gcol < VOUT)
                        orow[gcol] = stg[r * 128 + (col ^ swz)];
                }
            }
            __syncthreads();
        }
        // (end-of-tile sync included above; buffer (t&1) now reusable)
    }
}

// ===========================================================================
extern "C" void kernel_launch(void* const* d_in, const int* in_sizes, int n_in,
                              void* d_out, int out_size)
{
    const int*   alias_inputs = (const int*)  d_in[0];
    const float* ain   = (const float*)d_in[1];
    const float* aou   = (const float*)d_in[2];
    const int*   items = (const int*)  d_in[3];
    const int*   mask  = (const int*)  d_in[4];
    /* d_in[5] edge_index unused */
    const float* emb   = (const float*)d_in[6];
    const float* einw  = (const float*)d_in[7];
    const float* einb  = (const float*)d_in[8];
    const float* eouw  = (const float*)d_in[9];
    const float* eoub  = (const float*)d_in[10];
    const float* biah  = (const float*)d_in[11];
    const float* boah  = (const float*)d_in[12];
    const float* igw   = (const float*)d_in[13];
    const float* igb   = (const float*)d_in[14];
    const float* hgw   = (const float*)d_in[15];
    const float* hgb   = (const float*)d_in[16];
    const float* fc1w  = (const float*)d_in[17];
    const float* fc1b  = (const float*)d_in[18];
    const float* fc2w  = (const float*)d_in[19];
    const float* fc2b  = (const float*)d_in[20];
    const float* fc3w  = (const float*)d_in[21];
    float* out = (float*)d_out;

    cudaFuncSetAttribute(session_kernel,
                         cudaFuncAttributeMaxDynamicSharedMemorySize,
                         SM1_FLOATS * 4);
    cudaFuncSetAttribute(gemm_mma_kernel,
                         cudaFuncAttributeMaxDynamicSharedMemorySize,
                         GT_BYTES);

    split_kernel<<<(VOCAB * 16 + 255) / 256, 256>>>(emb);

    session_kernel<<<BATCH, 256, SM1_FLOATS * 4>>>(
        alias_inputs, ain, aou, items, mask, emb,
        einw, einb, eouw, eoub, biah, boah,
        igw, igb, hgw, hgb, fc1w, fc1b, fc2w, fc2b, fc3w);

    dim3 grid(8, (NVTILES + T_VTILES - 1) / T_VTILES, 1);
    gemm_mma_kernel<<<grid, 256, GT_BYTES>>>(out);
}